// round 3
// baseline (speedup 1.0000x reference)
#include <cuda_runtime.h>
#include <math.h>
#include <stdint.h>

#define NB 4
#define NT 4096
#define ND 1024
#define NH 64
#define SPLIT 2

// Scratch: tf32-rounded Q (pre-scaled by 1/8), K, V; split partials.
__device__ float g_Q[NB * NT * NH];
__device__ float g_K[NB * NT * NH];
__device__ float g_V[NB * NT * NH];
__device__ float g_Op[SPLIT][NB * NT * NH];
__device__ float g_ml[SPLIT][NB * NT][2];

__device__ __forceinline__ uint32_t f2tf(float f) {
    uint32_t u;
    asm("cvt.rna.tf32.f32 %0, %1;" : "=r"(u) : "f"(f));
    return u;
}

__device__ __forceinline__ void mma8(float d[4],
                                     uint32_t a0, uint32_t a1, uint32_t a2, uint32_t a3,
                                     uint32_t b0, uint32_t b1) {
    asm volatile(
        "mma.sync.aligned.m16n8k8.row.col.f32.tf32.tf32.f32 "
        "{%0,%1,%2,%3}, {%4,%5,%6,%7}, {%8,%9}, {%0,%1,%2,%3};"
        : "+f"(d[0]), "+f"(d[1]), "+f"(d[2]), "+f"(d[3])
        : "r"(a0), "r"(a1), "r"(a2), "r"(a3), "r"(b0), "r"(b1));
}

// float4-granular XOR swizzle on 64-float rows (conflict-free fragment access).
#define SW(r, c) (((r) << 6) + ((((c) >> 2) ^ ((r) & 7)) << 2) + ((c) & 3))

__device__ __forceinline__ void cp16(uint32_t dst, const void* src) {
    asm volatile("cp.async.cg.shared.global [%0], [%1], 16;" :: "r"(dst), "l"(src));
}
__device__ __forceinline__ void cp_commit() { asm volatile("cp.async.commit_group;"); }
template<int N> __device__ __forceinline__ void cp_wait() {
    asm volatile("cp.async.wait_group %0;" :: "n"(N));
}

// ---------------------------------------------------------------------------
// Kernel 1: fused QKV projection, tf32 mma, register-staged double buffering.
// 64 rows x 192 cols per CTA, 8 warps, 16-wide k-chunks, smem 20KB.
// ---------------------------------------------------------------------------
#define QPW 20  // smem pitch for 16-wide k-chunks

__global__ __launch_bounds__(256) void qkv_kernel(
    const float* __restrict__ x,
    const float* __restrict__ wq,
    const float* __restrict__ wk,
    const float* __restrict__ wv)
{
    __shared__ float sm[256 * QPW];  // rows 0-63: x | 64-127: wq | 128-191: wk | 192-255: wv
    const int t = threadIdx.x;
    const int row0 = blockIdx.x * 64;
    const int w = t >> 5, lane = t & 31, g = lane >> 2, t4 = lane & 3;
    const int wr = w & 3, wc = w >> 2;

    // Staging: thread t loads rows (t>>2)+64i, cols (t&3)*4, i=0..3.
    const float* srcs[4];
    srcs[0] = x  + (size_t)(row0 + (t >> 2)) * ND + (t & 3) * 4;
    srcs[1] = wq + (size_t)(t >> 2) * ND + (t & 3) * 4;
    srcs[2] = wk + (size_t)(t >> 2) * ND + (t & 3) * 4;
    srcs[3] = wv + (size_t)(t >> 2) * ND + (t & 3) * 4;

    float4 st[4];
#pragma unroll
    for (int i = 0; i < 4; i++) st[i] = *(const float4*)(srcs[i]);

    float acc[12][4];
#pragma unroll
    for (int nt = 0; nt < 12; nt++)
#pragma unroll
        for (int j = 0; j < 4; j++) acc[nt][j] = 0.0f;

    for (int k0 = 0; k0 < ND; k0 += 16) {
        // Store staged chunk (cvt to tf32 on the way in).
#pragma unroll
        for (int i = 0; i < 4; i++) {
            float4 v;
            v.x = __uint_as_float(f2tf(st[i].x));
            v.y = __uint_as_float(f2tf(st[i].y));
            v.z = __uint_as_float(f2tf(st[i].z));
            v.w = __uint_as_float(f2tf(st[i].w));
            *(float4*)&sm[((t >> 2) + 64 * i) * QPW + (t & 3) * 4] = v;
        }
        __syncthreads();
        // Prefetch next chunk into regs (overlaps with mma below).
        if (k0 + 16 < ND) {
#pragma unroll
            for (int i = 0; i < 4; i++)
                st[i] = *(const float4*)(srcs[i] + k0 + 16);
        }
#pragma unroll
        for (int ks8 = 0; ks8 < 2; ks8++) {
            int kk = ks8 * 8;
            uint32_t a0 = __float_as_uint(sm[(16 * wr + g) * QPW + kk + t4]);
            uint32_t a1 = __float_as_uint(sm[(16 * wr + g + 8) * QPW + kk + t4]);
            uint32_t a2 = __float_as_uint(sm[(16 * wr + g) * QPW + kk + t4 + 4]);
            uint32_t a3 = __float_as_uint(sm[(16 * wr + g + 8) * QPW + kk + t4 + 4]);
#pragma unroll
            for (int nt = 0; nt < 12; nt++) {
                int br = 64 + 96 * wc + 8 * nt + g;
                uint32_t b0 = __float_as_uint(sm[br * QPW + kk + t4]);
                uint32_t b1 = __float_as_uint(sm[br * QPW + kk + t4 + 4]);
                mma8(acc[nt], a0, a1, a2, a3, b0, b1);
            }
        }
        __syncthreads();
    }

    // Epilogue: route to Q/K/V, scale Q by 1/sqrt(64), round to tf32.
#pragma unroll
    for (int nt = 0; nt < 12; nt++) {
        int gc = 96 * wc + 8 * nt + 2 * t4;
        int mm = gc >> 6;
        int h = gc & 63;
        float* dst = (mm == 0) ? g_Q : (mm == 1) ? g_K : g_V;
        float sc = (mm == 0) ? 0.125f : 1.0f;
        int r1 = row0 + 16 * wr + g;
        dst[(size_t)r1 * NH + h]           = __uint_as_float(f2tf(acc[nt][0] * sc));
        dst[(size_t)r1 * NH + h + 1]       = __uint_as_float(f2tf(acc[nt][1] * sc));
        dst[(size_t)(r1 + 8) * NH + h]     = __uint_as_float(f2tf(acc[nt][2] * sc));
        dst[(size_t)(r1 + 8) * NH + h + 1] = __uint_as_float(f2tf(acc[nt][3] * sc));
    }
}

// ---------------------------------------------------------------------------
// Kernel 2: flash attention. BLOCK_M=64, BLOCK_N=64, 4 warps, split-KV.
// Q fragments in registers; K double-buffered + V single-buffered via cp.async;
// P never touches smem (permuted-k trick: C-frag of S feeds A-frag of GEMM2
// directly, with V rows read in the matching permuted order 2t4, 2t4+1).
// ---------------------------------------------------------------------------
__global__ __launch_bounds__(128) void attn_kernel()
{
    __shared__ float ks[2][64 * 64];  // 2 x 16KB
    __shared__ float vs[64 * 64];     // 16KB  (total 48KB static)

    const int b = blockIdx.y, q0 = blockIdx.x * 64, sp = blockIdx.z;
    const int t = threadIdx.x, w = t >> 5, lane = t & 31;
    const int g = lane >> 2, t4 = lane & 3;
    const int r0 = w * 16;

    const float* Qp = g_Q + ((size_t)b * NT + q0) * NH;
    const float* Kp = g_K + (size_t)b * NT * NH + (size_t)sp * (NT / SPLIT) * NH;
    const float* Vp = g_V + (size_t)b * NT * NH + (size_t)sp * (NT / SPLIT) * NH;

    const uint32_t ksb = (uint32_t)__cvta_generic_to_shared(&ks[0][0]);
    const uint32_t vsb = (uint32_t)__cvta_generic_to_shared(&vs[0]);

    // Q fragments: loop-invariant, registers.
    uint32_t q[8][4];
#pragma unroll
    for (int kk8 = 0; kk8 < 8; kk8++) {
        q[kk8][0] = __float_as_uint(Qp[(r0 + g) * NH + kk8 * 8 + t4]);
        q[kk8][1] = __float_as_uint(Qp[(r0 + g + 8) * NH + kk8 * 8 + t4]);
        q[kk8][2] = __float_as_uint(Qp[(r0 + g) * NH + kk8 * 8 + t4 + 4]);
        q[kk8][3] = __float_as_uint(Qp[(r0 + g + 8) * NH + kk8 * 8 + t4 + 4]);
    }

    float o[8][4];
    float m[2] = {-1e30f, -1e30f}, l[2] = {0.0f, 0.0f};
#pragma unroll
    for (int nt = 0; nt < 8; nt++)
#pragma unroll
        for (int j = 0; j < 4; j++) o[nt][j] = 0.0f;

    // Tile loader: 8 x 16B per thread; rows (t>>4)+8i, col group (t&15)*4.
    const int lr = t >> 4, lc = (t & 15) * 4;

    // Prologue: issue K(0) then V(0) as two groups.
#pragma unroll
    for (int i = 0; i < 8; i++)
        cp16(ksb + (uint32_t)SW(lr + 8 * i, lc) * 4,
             Kp + (size_t)(lr + 8 * i) * NH + lc);
    cp_commit();
#pragma unroll
    for (int i = 0; i < 8; i++)
        cp16(vsb + (uint32_t)SW(lr + 8 * i, lc) * 4,
             Vp + (size_t)(lr + 8 * i) * NH + lc);
    cp_commit();

    const int NIT = (NT / SPLIT) / 64;  // 32

    for (int it = 0; it < NIT; it++) {
        const int p = it & 1;
        // K(it) ready (leaves V(it) possibly in flight).
        cp_wait<1>();
        __syncthreads();
        // Issue K(it+1) into the other buffer (empty group at the end is fine).
        if (it + 1 < NIT) {
#pragma unroll
            for (int i = 0; i < 8; i++)
                cp16(ksb + (uint32_t)((p ^ 1) * 4096 + SW(lr + 8 * i, lc)) * 4,
                     Kp + (size_t)((it + 1) * 64 + lr + 8 * i) * NH + lc);
        }
        cp_commit();

        // GEMM1: S = Q @ K^T (1/sqrt(hd) folded into Q).
        float s[8][4];
#pragma unroll
        for (int nt = 0; nt < 8; nt++)
            s[nt][0] = s[nt][1] = s[nt][2] = s[nt][3] = 0.0f;
#pragma unroll
        for (int kk8 = 0; kk8 < 8; kk8++) {
            int k0 = kk8 * 8;
#pragma unroll
            for (int nt = 0; nt < 8; nt++) {
                uint32_t b0 = __float_as_uint(ks[p][SW(nt * 8 + g, k0 + t4)]);
                uint32_t b1 = __float_as_uint(ks[p][SW(nt * 8 + g, k0 + t4 + 4)]);
                mma8(s[nt], q[kk8][0], q[kk8][1], q[kk8][2], q[kk8][3], b0, b1);
            }
        }

        // Online softmax (row stats across quad via shfl).
        float mx0 = -1e30f, mx1 = -1e30f;
#pragma unroll
        for (int nt = 0; nt < 8; nt++) {
            mx0 = fmaxf(mx0, fmaxf(s[nt][0], s[nt][1]));
            mx1 = fmaxf(mx1, fmaxf(s[nt][2], s[nt][3]));
        }
        mx0 = fmaxf(mx0, __shfl_xor_sync(0xffffffffu, mx0, 1));
        mx0 = fmaxf(mx0, __shfl_xor_sync(0xffffffffu, mx0, 2));
        mx1 = fmaxf(mx1, __shfl_xor_sync(0xffffffffu, mx1, 1));
        mx1 = fmaxf(mx1, __shfl_xor_sync(0xffffffffu, mx1, 2));
        float mn0 = fmaxf(m[0], mx0), mn1 = fmaxf(m[1], mx1);
        float c0 = __expf(m[0] - mn0), c1 = __expf(m[1] - mn1);
        float sum0 = 0.0f, sum1 = 0.0f;
#pragma unroll
        for (int nt = 0; nt < 8; nt++) {
            s[nt][0] = __expf(s[nt][0] - mn0);
            s[nt][1] = __expf(s[nt][1] - mn0);
            s[nt][2] = __expf(s[nt][2] - mn1);
            s[nt][3] = __expf(s[nt][3] - mn1);
            sum0 += s[nt][0] + s[nt][1];
            sum1 += s[nt][2] + s[nt][3];
            o[nt][0] *= c0; o[nt][1] *= c0;
            o[nt][2] *= c1; o[nt][3] *= c1;
        }
        sum0 += __shfl_xor_sync(0xffffffffu, sum0, 1);
        sum0 += __shfl_xor_sync(0xffffffffu, sum0, 2);
        sum1 += __shfl_xor_sync(0xffffffffu, sum1, 1);
        sum1 += __shfl_xor_sync(0xffffffffu, sum1, 2);
        l[0] = l[0] * c0 + sum0;
        l[1] = l[1] * c1 + sum1;
        m[0] = mn0;
        m[1] = mn1;

        // V(it) ready.
        cp_wait<1>();
        __syncthreads();

        // GEMM2: O += P @ V. A-frag = S C-frag directly (permuted k);
        // B reads V rows kb*8+2t4, kb*8+2t4+1 to match the permutation.
#pragma unroll
        for (int kb = 0; kb < 8; kb++) {
            uint32_t a0 = f2tf(s[kb][0]);
            uint32_t a1 = f2tf(s[kb][2]);
            uint32_t a2 = f2tf(s[kb][1]);
            uint32_t a3 = f2tf(s[kb][3]);
#pragma unroll
            for (int nt = 0; nt < 8; nt++) {
                uint32_t b0 = __float_as_uint(vs[SW(kb * 8 + 2 * t4, nt * 8 + g)]);
                uint32_t b1 = __float_as_uint(vs[SW(kb * 8 + 2 * t4 + 1, nt * 8 + g)]);
                mma8(o[nt], a0, a1, a2, a3, b0, b1);
            }
        }
        __syncthreads();  // all reads of vs done before refill

        if (it + 1 < NIT) {
#pragma unroll
            for (int i = 0; i < 8; i++)
                cp16(vsb + (uint32_t)SW(lr + 8 * i, lc) * 4,
                     Vp + (size_t)((it + 1) * 64 + lr + 8 * i) * NH + lc);
        }
        cp_commit();
    }

    // Epilogue: unnormalized numerator + (m, l) per split.
    float* Op = g_Op[sp] + ((size_t)b * NT + q0) * NH;
#pragma unroll
    for (int nt = 0; nt < 8; nt++) {
        int c = nt * 8 + 2 * t4;
        *(float2*)&Op[(size_t)(r0 + g) * NH + c]     = make_float2(o[nt][0], o[nt][1]);
        *(float2*)&Op[(size_t)(r0 + g + 8) * NH + c] = make_float2(o[nt][2], o[nt][3]);
    }
    if (t4 == 0) {
        int rr = b * NT + q0;
        g_ml[sp][rr + r0 + g][0] = m[0];
        g_ml[sp][rr + r0 + g][1] = l[0];
        g_ml[sp][rr + r0 + g + 8][0] = m[1];
        g_ml[sp][rr + r0 + g + 8][1] = l[1];
    }
}

// ---------------------------------------------------------------------------
// Kernel 3: merge the 2 KV-splits.
// ---------------------------------------------------------------------------
__global__ __launch_bounds__(256) void combine_kernel(float* __restrict__ out)
{
    int row = blockIdx.x * 4 + (threadIdx.x >> 6);
    int c = threadIdx.x & 63;
    float m0 = g_ml[0][row][0], l0 = g_ml[0][row][1];
    float m1 = g_ml[1][row][0], l1 = g_ml[1][row][1];
    float M = fmaxf(m0, m1);
    float e0 = __expf(m0 - M), e1 = __expf(m1 - M);
    float L = e0 * l0 + e1 * l1;
    size_t idx = (size_t)row * NH + c;
    out[idx] = (e0 * g_Op[0][idx] + e1 * g_Op[1][idx]) / L;
}

// ---------------------------------------------------------------------------
extern "C" void kernel_launch(void* const* d_in, const int* in_sizes, int n_in,
                              void* d_out, int out_size)
{
    const float* x  = (const float*)d_in[0];
    const float* wq = (const float*)d_in[1];
    const float* wk = (const float*)d_in[2];
    const float* wv = (const float*)d_in[3];
    float* out = (float*)d_out;
    (void)in_sizes; (void)n_in; (void)out_size;

    // Prefer max smem carveout for the 48KB-resident attention kernel
    // (idempotent host-side attribute set; not a stream op, capture-safe).
    cudaFuncSetAttribute((const void*)attn_kernel,
                         cudaFuncAttributePreferredSharedMemoryCarveout,
                         cudaSharedmemCarveoutMaxShared);

    qkv_kernel<<<(NB * NT) / 64, 256>>>(x, wq, wk, wv);
    attn_kernel<<<dim3(NT / 64, NB, SPLIT), 128>>>();
    combine_kernel<<<(NB * NT) / 4, 256>>>(out);
}

// round 4
// speedup vs baseline: 1.5618x; 1.5618x over previous
#include <cuda_runtime.h>
#include <math.h>
#include <stdint.h>

#define NB 4
#define NT 4096
#define ND 1024
#define NH 64
#define SPLIT 4

// Scratch: tf32-rounded Q (pre-scaled by 1/8), K, V; split partials.
__device__ float g_Q[NB * NT * NH];
__device__ float g_K[NB * NT * NH];
__device__ float g_V[NB * NT * NH];
__device__ float g_Op[SPLIT][NB * NT * NH];
__device__ float g_ml[SPLIT][NB * NT][2];

__device__ __forceinline__ uint32_t f2tf(float f) {
    uint32_t u;
    asm("cvt.rna.tf32.f32 %0, %1;" : "=r"(u) : "f"(f));
    return u;
}

__device__ __forceinline__ void mma8(float d[4],
                                     uint32_t a0, uint32_t a1, uint32_t a2, uint32_t a3,
                                     uint32_t b0, uint32_t b1) {
    asm volatile(
        "mma.sync.aligned.m16n8k8.row.col.f32.tf32.tf32.f32 "
        "{%0,%1,%2,%3}, {%4,%5,%6,%7}, {%8,%9}, {%0,%1,%2,%3};"
        : "+f"(d[0]), "+f"(d[1]), "+f"(d[2]), "+f"(d[3])
        : "r"(a0), "r"(a1), "r"(a2), "r"(a3), "r"(b0), "r"(b1));
}

// float4-granular XOR swizzle on 64-float rows (conflict-free fragment access).
#define SW(r, c) (((r) << 6) + ((((c) >> 2) ^ ((r) & 7)) << 2) + ((c) & 3))

__device__ __forceinline__ void cp16(uint32_t dst, const void* src) {
    asm volatile("cp.async.cg.shared.global [%0], [%1], 16;" :: "r"(dst), "l"(src));
}
__device__ __forceinline__ void cp_commit() { asm volatile("cp.async.commit_group;"); }
template<int N> __device__ __forceinline__ void cp_wait() {
    asm volatile("cp.async.wait_group %0;" :: "n"(N));
}

// ---------------------------------------------------------------------------
// Kernel 1: fused QKV projection (Round-2 proven version, 89us).
// 64 rows x 192 cols per CTA, 8 warps, 32-wide k-chunks.
// ---------------------------------------------------------------------------
#define PW 36

__global__ __launch_bounds__(256) void qkv_kernel(
    const float* __restrict__ x,
    const float* __restrict__ wq,
    const float* __restrict__ wk,
    const float* __restrict__ wv)
{
    __shared__ float sm[256 * PW];
    const int t = threadIdx.x;
    const int row0 = blockIdx.x * 64;
    const int w = t >> 5, lane = t & 31, g = lane >> 2, t4 = lane & 3;
    const int wr = w & 3, wc = w >> 2;

    const float* srcs[8];
#pragma unroll
    for (int i = 0; i < 8; i++) {
        int r = (t >> 3) + 32 * i;
        const float* p;
        if (r < 64)       p = x  + (size_t)(row0 + r) * ND;
        else if (r < 128) p = wq + (size_t)(r - 64) * ND;
        else if (r < 192) p = wk + (size_t)(r - 128) * ND;
        else              p = wv + (size_t)(r - 192) * ND;
        srcs[i] = p + (t & 7) * 4;
    }

    float acc[12][4];
#pragma unroll
    for (int nt = 0; nt < 12; nt++)
#pragma unroll
        for (int j = 0; j < 4; j++) acc[nt][j] = 0.0f;

    for (int k0 = 0; k0 < ND; k0 += 32) {
        __syncthreads();
#pragma unroll
        for (int i = 0; i < 8; i++) {
            int r = (t >> 3) + 32 * i;
            float4 v = *(const float4*)(srcs[i] + k0);
            float* d = &sm[r * PW + (t & 7) * 4];
            d[0] = __uint_as_float(f2tf(v.x));
            d[1] = __uint_as_float(f2tf(v.y));
            d[2] = __uint_as_float(f2tf(v.z));
            d[3] = __uint_as_float(f2tf(v.w));
        }
        __syncthreads();
#pragma unroll
        for (int ks8 = 0; ks8 < 4; ks8++) {
            int kk = ks8 * 8;
            uint32_t a0 = __float_as_uint(sm[(16 * wr + g) * PW + kk + t4]);
            uint32_t a1 = __float_as_uint(sm[(16 * wr + g + 8) * PW + kk + t4]);
            uint32_t a2 = __float_as_uint(sm[(16 * wr + g) * PW + kk + t4 + 4]);
            uint32_t a3 = __float_as_uint(sm[(16 * wr + g + 8) * PW + kk + t4 + 4]);
#pragma unroll
            for (int nt = 0; nt < 12; nt++) {
                int br = 64 + 96 * wc + 8 * nt + g;
                uint32_t b0 = __float_as_uint(sm[br * PW + kk + t4]);
                uint32_t b1 = __float_as_uint(sm[br * PW + kk + t4 + 4]);
                mma8(acc[nt], a0, a1, a2, a3, b0, b1);
            }
        }
    }

#pragma unroll
    for (int nt = 0; nt < 12; nt++) {
        int gc = 96 * wc + 8 * nt + 2 * t4;
        int mm = gc >> 6;
        int h = gc & 63;
        float* dst = (mm == 0) ? g_Q : (mm == 1) ? g_K : g_V;
        float sc = (mm == 0) ? 0.125f : 1.0f;
        int r1 = row0 + 16 * wr + g;
        dst[(size_t)r1 * NH + h]           = __uint_as_float(f2tf(acc[nt][0] * sc));
        dst[(size_t)r1 * NH + h + 1]       = __uint_as_float(f2tf(acc[nt][1] * sc));
        dst[(size_t)(r1 + 8) * NH + h]     = __uint_as_float(f2tf(acc[nt][2] * sc));
        dst[(size_t)(r1 + 8) * NH + h + 1] = __uint_as_float(f2tf(acc[nt][3] * sc));
    }
}

// ---------------------------------------------------------------------------
// Kernel 2: flash attention. BLOCK_M=128, BLOCK_N=64, 4 warps (32 rows/warp,
// 2 m-tiles), split-KV=4. B fragments (K and V) loaded ONCE and shared by
// both m-tiles -> LDS per FLOP halved vs BM=64. Q tile in smem (loaded once
// per CTA via cp.async). P never touches smem (permuted-k trick).
// Dynamic smem: Q 32KB | K 2x16KB | V 16KB = 80KB.
// ---------------------------------------------------------------------------
#define ATTN_SMEM_BYTES (20480 * 4)

__global__ __launch_bounds__(128) void attn_kernel()
{
    extern __shared__ float smem[];
    float* qs = smem;                    // 128x64
    float* ks0 = smem + 8192;            // 64x64 (buffer 0)
    float* ks1 = smem + 12288;           // 64x64 (buffer 1)
    float* vs  = smem + 16384;           // 64x64

    const int b = blockIdx.y, q0 = blockIdx.x * 128, sp = blockIdx.z;
    const int t = threadIdx.x, w = t >> 5, lane = t & 31;
    const int g = lane >> 2, t4 = lane & 3;
    const int r0 = w * 32;  // warp owns rows [r0, r0+32)

    const float* Qp = g_Q + ((size_t)b * NT + q0) * NH;
    const float* Kp = g_K + (size_t)b * NT * NH + (size_t)sp * (NT / SPLIT) * NH;
    const float* Vp = g_V + (size_t)b * NT * NH + (size_t)sp * (NT / SPLIT) * NH;

    const uint32_t smb = (uint32_t)__cvta_generic_to_shared(smem);
    const uint32_t qsb = smb;
    const uint32_t ksb = smb + 8192 * 4;
    const uint32_t vsb = smb + 16384 * 4;

    // Tile loader mapping: rows (t>>4)+8i, col group (t&15)*4.
    const int lr = t >> 4, lc = (t & 15) * 4;

    // Prologue: group A = Q(128 rows) + K(0); group B = V(0).
#pragma unroll
    for (int i = 0; i < 16; i++)
        cp16(qsb + (uint32_t)(((lr + 8 * i) << 6) +
                   ((((lc) >> 2) ^ ((lr + 8 * i) & 7)) << 2)) * 4,
             Qp + (size_t)(lr + 8 * i) * NH + lc);
#pragma unroll
    for (int i = 0; i < 8; i++)
        cp16(ksb + (uint32_t)SW(lr + 8 * i, lc) * 4,
             Kp + (size_t)(lr + 8 * i) * NH + lc);
    cp_commit();
#pragma unroll
    for (int i = 0; i < 8; i++)
        cp16(vsb + (uint32_t)SW(lr + 8 * i, lc) * 4,
             Vp + (size_t)(lr + 8 * i) * NH + lc);
    cp_commit();

    float o[2][8][4];
    float m[2][2], l[2][2];
#pragma unroll
    for (int mt = 0; mt < 2; mt++) {
        m[mt][0] = m[mt][1] = -1e30f;
        l[mt][0] = l[mt][1] = 0.0f;
#pragma unroll
        for (int nt = 0; nt < 8; nt++)
#pragma unroll
            for (int j = 0; j < 4; j++) o[mt][nt][j] = 0.0f;
    }

    const int NIT = (NT / SPLIT) / 64;  // 16

    for (int it = 0; it < NIT; it++) {
        const float* ksp = (it & 1) ? ks1 : ks0;
        const uint32_t knb = (it & 1) ? ksb : (ksb + 4096 * 4);
        // Q + K(it) ready.
        cp_wait<1>();
        __syncthreads();
        // Issue K(it+1) into the other buffer.
        if (it + 1 < NIT) {
#pragma unroll
            for (int i = 0; i < 8; i++)
                cp16(knb + (uint32_t)SW(lr + 8 * i, lc) * 4,
                     Kp + (size_t)((it + 1) * 64 + lr + 8 * i) * NH + lc);
        }
        cp_commit();

        // GEMM1: S = Q @ K^T. B frags shared across both m-tiles.
        float s[2][8][4];
#pragma unroll
        for (int mt = 0; mt < 2; mt++)
#pragma unroll
            for (int nt = 0; nt < 8; nt++)
                s[mt][nt][0] = s[mt][nt][1] = s[mt][nt][2] = s[mt][nt][3] = 0.0f;
#pragma unroll
        for (int kk8 = 0; kk8 < 8; kk8++) {
            int k0 = kk8 * 8;
            uint32_t a[2][4];
#pragma unroll
            for (int mt = 0; mt < 2; mt++) {
                int ar = r0 + 16 * mt;
                a[mt][0] = __float_as_uint(qs[SW(ar + g, k0 + t4)]);
                a[mt][1] = __float_as_uint(qs[SW(ar + g + 8, k0 + t4)]);
                a[mt][2] = __float_as_uint(qs[SW(ar + g, k0 + t4 + 4)]);
                a[mt][3] = __float_as_uint(qs[SW(ar + g + 8, k0 + t4 + 4)]);
            }
#pragma unroll
            for (int nt = 0; nt < 8; nt++) {
                uint32_t b0 = __float_as_uint(ksp[SW(nt * 8 + g, k0 + t4)]);
                uint32_t b1 = __float_as_uint(ksp[SW(nt * 8 + g, k0 + t4 + 4)]);
                mma8(s[0][nt], a[0][0], a[0][1], a[0][2], a[0][3], b0, b1);
                mma8(s[1][nt], a[1][0], a[1][1], a[1][2], a[1][3], b0, b1);
            }
        }

        // Online softmax per m-tile (row stats across quad via shfl).
#pragma unroll
        for (int mt = 0; mt < 2; mt++) {
            float mx0 = -1e30f, mx1 = -1e30f;
#pragma unroll
            for (int nt = 0; nt < 8; nt++) {
                mx0 = fmaxf(mx0, fmaxf(s[mt][nt][0], s[mt][nt][1]));
                mx1 = fmaxf(mx1, fmaxf(s[mt][nt][2], s[mt][nt][3]));
            }
            mx0 = fmaxf(mx0, __shfl_xor_sync(0xffffffffu, mx0, 1));
            mx0 = fmaxf(mx0, __shfl_xor_sync(0xffffffffu, mx0, 2));
            mx1 = fmaxf(mx1, __shfl_xor_sync(0xffffffffu, mx1, 1));
            mx1 = fmaxf(mx1, __shfl_xor_sync(0xffffffffu, mx1, 2));
            float mn0 = fmaxf(m[mt][0], mx0), mn1 = fmaxf(m[mt][1], mx1);
            float c0 = __expf(m[mt][0] - mn0), c1 = __expf(m[mt][1] - mn1);
            float sum0 = 0.0f, sum1 = 0.0f;
#pragma unroll
            for (int nt = 0; nt < 8; nt++) {
                s[mt][nt][0] = __expf(s[mt][nt][0] - mn0);
                s[mt][nt][1] = __expf(s[mt][nt][1] - mn0);
                s[mt][nt][2] = __expf(s[mt][nt][2] - mn1);
                s[mt][nt][3] = __expf(s[mt][nt][3] - mn1);
                sum0 += s[mt][nt][0] + s[mt][nt][1];
                sum1 += s[mt][nt][2] + s[mt][nt][3];
                o[mt][nt][0] *= c0; o[mt][nt][1] *= c0;
                o[mt][nt][2] *= c1; o[mt][nt][3] *= c1;
            }
            sum0 += __shfl_xor_sync(0xffffffffu, sum0, 1);
            sum0 += __shfl_xor_sync(0xffffffffu, sum0, 2);
            sum1 += __shfl_xor_sync(0xffffffffu, sum1, 1);
            sum1 += __shfl_xor_sync(0xffffffffu, sum1, 2);
            l[mt][0] = l[mt][0] * c0 + sum0;
            l[mt][1] = l[mt][1] * c1 + sum1;
            m[mt][0] = mn0;
            m[mt][1] = mn1;
        }

        // V(it) ready.
        cp_wait<1>();
        __syncthreads();

        // GEMM2: O += P @ V. A = S C-frag directly (permuted k); V rows read
        // in matching permuted order. B frags shared across both m-tiles.
#pragma unroll
        for (int kb = 0; kb < 8; kb++) {
            uint32_t a[2][4];
#pragma unroll
            for (int mt = 0; mt < 2; mt++) {
                a[mt][0] = f2tf(s[mt][kb][0]);
                a[mt][1] = f2tf(s[mt][kb][2]);
                a[mt][2] = f2tf(s[mt][kb][1]);
                a[mt][3] = f2tf(s[mt][kb][3]);
            }
#pragma unroll
            for (int nt = 0; nt < 8; nt++) {
                uint32_t b0 = __float_as_uint(vs[SW(kb * 8 + 2 * t4, nt * 8 + g)]);
                uint32_t b1 = __float_as_uint(vs[SW(kb * 8 + 2 * t4 + 1, nt * 8 + g)]);
                mma8(o[0][nt], a[0][0], a[0][1], a[0][2], a[0][3], b0, b1);
                mma8(o[1][nt], a[1][0], a[1][1], a[1][2], a[1][3], b0, b1);
            }
        }
        __syncthreads();  // all reads of vs done before refill

        if (it + 1 < NIT) {
#pragma unroll
            for (int i = 0; i < 8; i++)
                cp16(vsb + (uint32_t)SW(lr + 8 * i, lc) * 4,
                     Vp + (size_t)((it + 1) * 64 + lr + 8 * i) * NH + lc);
        }
        cp_commit();
    }

    // Epilogue: unnormalized numerator + (m, l) per split.
    float* Op = g_Op[sp] + ((size_t)b * NT + q0) * NH;
#pragma unroll
    for (int mt = 0; mt < 2; mt++) {
        int ar = r0 + 16 * mt;
#pragma unroll
        for (int nt = 0; nt < 8; nt++) {
            int c = nt * 8 + 2 * t4;
            *(float2*)&Op[(size_t)(ar + g) * NH + c] =
                make_float2(o[mt][nt][0], o[mt][nt][1]);
            *(float2*)&Op[(size_t)(ar + g + 8) * NH + c] =
                make_float2(o[mt][nt][2], o[mt][nt][3]);
        }
        if (t4 == 0) {
            int rr = b * NT + q0;
            g_ml[sp][rr + ar + g][0] = m[mt][0];
            g_ml[sp][rr + ar + g][1] = l[mt][0];
            g_ml[sp][rr + ar + g + 8][0] = m[mt][1];
            g_ml[sp][rr + ar + g + 8][1] = l[mt][1];
        }
    }
}

// ---------------------------------------------------------------------------
// Kernel 3: merge the SPLIT KV-splits.
// ---------------------------------------------------------------------------
__global__ __launch_bounds__(256) void combine_kernel(float* __restrict__ out)
{
    int row = blockIdx.x * 4 + (threadIdx.x >> 6);
    int c = threadIdx.x & 63;
    float M = -1e30f;
#pragma unroll
    for (int sp = 0; sp < SPLIT; sp++) M = fmaxf(M, g_ml[sp][row][0]);
    float L = 0.0f, acc = 0.0f;
    size_t idx = (size_t)row * NH + c;
#pragma unroll
    for (int sp = 0; sp < SPLIT; sp++) {
        float e = __expf(g_ml[sp][row][0] - M);
        L += e * g_ml[sp][row][1];
        acc += e * g_Op[sp][idx];
    }
    out[idx] = acc / L;
}

// ---------------------------------------------------------------------------
extern "C" void kernel_launch(void* const* d_in, const int* in_sizes, int n_in,
                              void* d_out, int out_size)
{
    const float* x  = (const float*)d_in[0];
    const float* wq = (const float*)d_in[1];
    const float* wk = (const float*)d_in[2];
    const float* wv = (const float*)d_in[3];
    float* out = (float*)d_out;
    (void)in_sizes; (void)n_in; (void)out_size;

    cudaFuncSetAttribute((const void*)attn_kernel,
                         cudaFuncAttributeMaxDynamicSharedMemorySize,
                         ATTN_SMEM_BYTES);
    cudaFuncSetAttribute((const void*)attn_kernel,
                         cudaFuncAttributePreferredSharedMemoryCarveout,
                         cudaSharedmemCarveoutMaxShared);

    qkv_kernel<<<(NB * NT) / 64, 256>>>(x, wq, wk, wv);
    attn_kernel<<<dim3(NT / 128, NB, SPLIT), 128, ATTN_SMEM_BYTES>>>();
    combine_kernel<<<(NB * NT) / 4, 256>>>(out);
}

// round 6
// speedup vs baseline: 1.8706x; 1.1977x over previous
#include <cuda_runtime.h>
#include <math.h>
#include <stdint.h>

#define NB 4
#define NT 4096
#define ND 1024
#define NH 64
#define SPLIT 4

// Scratch: tf32-rounded Q (pre-scaled by 1/8), K, V; split partials.
__device__ float g_Q[NB * NT * NH];
__device__ float g_K[NB * NT * NH];
__device__ float g_V[NB * NT * NH];
__device__ float g_Op[SPLIT][NB * NT * NH];
__device__ float g_ml[SPLIT][NB * NT][2];
// tf32-converted, pair-permuted weights: rows 0-63 wq | 64-127 wk | 128-191 wv.
__device__ float g_Wp[192 * ND];

__device__ __forceinline__ uint32_t f2tf(float f) {
    uint32_t u;
    asm("cvt.rna.tf32.f32 %0, %1;" : "=r"(u) : "f"(f));
    return u;
}

__device__ __forceinline__ void mma8(float d[4],
                                     uint32_t a0, uint32_t a1, uint32_t a2, uint32_t a3,
                                     uint32_t b0, uint32_t b1) {
    asm volatile(
        "mma.sync.aligned.m16n8k8.row.col.f32.tf32.tf32.f32 "
        "{%0,%1,%2,%3}, {%4,%5,%6,%7}, {%8,%9}, {%0,%1,%2,%3};"
        : "+f"(d[0]), "+f"(d[1]), "+f"(d[2]), "+f"(d[3])
        : "r"(a0), "r"(a1), "r"(a2), "r"(a3), "r"(b0), "r"(b1));
}

// float4-granular XOR swizzle on 64-float rows (attention tiles, proven).
#define SW(r, c) (((r) << 6) + ((((c) >> 2) ^ ((r) & 7)) << 2) + ((c) & 3))

__device__ __forceinline__ void cp16(uint32_t dst, const void* src) {
    asm volatile("cp.async.cg.shared.global [%0], [%1], 16;" :: "r"(dst), "l"(src));
}
__device__ __forceinline__ void cp_commit() { asm volatile("cp.async.commit_group;"); }
template<int N> __device__ __forceinline__ void cp_wait() {
    asm volatile("cp.async.wait_group %0;" :: "n"(N));
}

// ---------------------------------------------------------------------------
// Kernel 0: weight prepass. tf32-round and pair-permute columns per 8-block:
// stored position 2(j&3)+(j>>2) holds logical k-offset j, so (t4, t4+4)
// fragment halves become adjacent -> LDS.64 in the GEMM.
// ---------------------------------------------------------------------------
__global__ __launch_bounds__(256) void prep_w_kernel(
    const float* __restrict__ wq,
    const float* __restrict__ wk,
    const float* __restrict__ wv)
{
    int idx = blockIdx.x * 256 + threadIdx.x;  // 192*1024
    int row = idx >> 10, k = idx & 1023;
    const float* src = (row < 64) ? wq + (size_t)row * ND
                     : (row < 128) ? wk + (size_t)(row - 64) * ND
                     : wv + (size_t)(row - 128) * ND;
    int j = k & 7;
    int p = (k & ~7) | (2 * (j & 3)) | (j >> 2);
    g_Wp[(size_t)row * ND + p] = __uint_as_float(f2tf(src[k]));
}

// ---------------------------------------------------------------------------
// Kernel 1: fused QKV projection. cp.async double-buffered 32-wide k-chunks.
// x tile raw fp32 (pitch 36, cvt at A-frag load); W tile pre-converted +
// pair-permuted -> B frags via LDS.64, no cvt. 8 warps as 2 row-groups
// (32 rows, 2 m-tiles) x 4 col-groups (48 cols, 6 n-tiles).
// Dynamic smem: x 2x(64x36) + W 2x(192x32) = 67584 B.
// ---------------------------------------------------------------------------
#define XPW 36
#define QKV_SMEM_BYTES (16896 * 4)

__device__ __forceinline__ void qkv_issue(uint32_t xbase, uint32_t wbase,
                                          const float* xsrc, int k0, int t)
{
    // x: 64 rows x 8 chunks = 512 cp16 -> 2 per thread.
#pragma unroll
    for (int i = 0; i < 2; i++) {
        int c = t * 2 + i;
        int row = c >> 3, j = c & 7;
        cp16(xbase + (uint32_t)(row * XPW + j * 4) * 4,
             xsrc + (size_t)row * ND + k0 + j * 4);
    }
    // W: 192 rows x 8 chunks = 1536 cp16 -> 6 per thread. Pair-granule swizzle:
    // 8B-granule index (2j) XOR'd by (row&3)<<2 (keeps 16B chunks aligned).
#pragma unroll
    for (int i = 0; i < 6; i++) {
        int c = t + 256 * i;
        int row = c >> 3, j = c & 7;
        uint32_t gran = (uint32_t)((2 * j) ^ ((row & 3) << 2));
        cp16(wbase + (uint32_t)(row * 32 + gran * 2) * 4,
             g_Wp + (size_t)row * ND + k0 + j * 4);
    }
}

__global__ __launch_bounds__(256) void qkv_kernel(const float* __restrict__ x)
{
    extern __shared__ float qsm[];
    const int t = threadIdx.x;
    const int row0 = blockIdx.x * 64;
    const int w = t >> 5, lane = t & 31, g = lane >> 2, t4 = lane & 3;
    const int wr = w & 1, wc = w >> 1;  // 2 row-groups x 4 col-groups

    const uint32_t smb = (uint32_t)__cvta_generic_to_shared(qsm);
    // float offsets: xb0=0, xb1=2304, wb0=4608, wb1=10752
    const uint32_t xoffs[2] = {smb, smb + 2304u * 4};
    const uint32_t woffs[2] = {smb + 4608u * 4, smb + 10752u * 4};
    float* const xbuf[2] = {qsm, qsm + 2304};
    float* const wbuf[2] = {qsm + 4608, qsm + 10752};

    const float* xsrc = x + (size_t)row0 * ND;

    float acc[2][6][4];
#pragma unroll
    for (int mt = 0; mt < 2; mt++)
#pragma unroll
        for (int nt = 0; nt < 6; nt++)
#pragma unroll
            for (int j = 0; j < 4; j++) acc[mt][nt][j] = 0.0f;

    // Prologue: chunk 0.
    qkv_issue(xoffs[0], woffs[0], xsrc, 0, t);
    cp_commit();

    for (int it = 0; it < 32; it++) {
        const int p = it & 1;
        cp_wait<0>();        // chunk `it` complete (only group in flight)
        __syncthreads();     // all warps done with buffer p^1 -> safe to refill
        if (it + 1 < 32) {
            qkv_issue(xoffs[p ^ 1], woffs[p ^ 1], xsrc, (it + 1) * 32, t);
            cp_commit();
        }

        const float* xb = xbuf[p];
        const float* wb = wbuf[p];
#pragma unroll
        for (int ks8 = 0; ks8 < 4; ks8++) {
            int kk = ks8 * 8;
            uint32_t a[2][4];
#pragma unroll
            for (int mt = 0; mt < 2; mt++) {
                int R = 32 * wr + 16 * mt;
                a[mt][0] = f2tf(xb[(R + g) * XPW + kk + t4]);
                a[mt][1] = f2tf(xb[(R + g + 8) * XPW + kk + t4]);
                a[mt][2] = f2tf(xb[(R + g) * XPW + kk + t4 + 4]);
                a[mt][3] = f2tf(xb[(R + g + 8) * XPW + kk + t4 + 4]);
            }
#pragma unroll
            for (int nt = 0; nt < 6; nt++) {
                int nrow = 48 * wc + 8 * nt + g;
                uint32_t gran = (uint32_t)((4 * ks8 + t4) ^ ((nrow & 3) << 2));
                float2 bv = *(const float2*)&wb[nrow * 32 + gran * 2];
                uint32_t b0 = __float_as_uint(bv.x);  // logical k = kk+t4
                uint32_t b1 = __float_as_uint(bv.y);  // logical k = kk+t4+4
                mma8(acc[0][nt], a[0][0], a[0][1], a[0][2], a[0][3], b0, b1);
                mma8(acc[1][nt], a[1][0], a[1][1], a[1][2], a[1][3], b0, b1);
            }
        }
    }

    // Epilogue: route to Q/K/V (standard layout), scale Q, round to tf32.
#pragma unroll
    for (int mt = 0; mt < 2; mt++)
#pragma unroll
        for (int nt = 0; nt < 6; nt++) {
            int gc = 48 * wc + 8 * nt + 2 * t4;
            int mm = gc >> 6;
            int h = gc & 63;
            float* dst = (mm == 0) ? g_Q : (mm == 1) ? g_K : g_V;
            float sc = (mm == 0) ? 0.125f : 1.0f;
            int r1 = row0 + 32 * wr + 16 * mt + g;
            dst[(size_t)r1 * NH + h]           = __uint_as_float(f2tf(acc[mt][nt][0] * sc));
            dst[(size_t)r1 * NH + h + 1]       = __uint_as_float(f2tf(acc[mt][nt][1] * sc));
            dst[(size_t)(r1 + 8) * NH + h]     = __uint_as_float(f2tf(acc[mt][nt][2] * sc));
            dst[(size_t)(r1 + 8) * NH + h + 1] = __uint_as_float(f2tf(acc[mt][nt][3] * sc));
        }
}

// ---------------------------------------------------------------------------
// Kernel 2: flash attention (Round-4 proven version, ~113us). BLOCK_M=128,
// BLOCK_N=64, 4 warps (2 m-tiles each), split-KV=4, permuted-k P trick.
// Dynamic smem: Q 32KB | K 2x16KB | V 16KB = 80KB.
// ---------------------------------------------------------------------------
#define ATTN_SMEM_BYTES (20480 * 4)

__global__ __launch_bounds__(128) void attn_kernel()
{
    extern __shared__ float smem[];
    float* qs = smem;                    // 128x64
    float* ks0 = smem + 8192;            // 64x64 (buffer 0)
    float* ks1 = smem + 12288;           // 64x64 (buffer 1)
    float* vs  = smem + 16384;           // 64x64

    const int b = blockIdx.y, q0 = blockIdx.x * 128, sp = blockIdx.z;
    const int t = threadIdx.x, w = t >> 5, lane = t & 31;
    const int g = lane >> 2, t4 = lane & 3;
    const int r0 = w * 32;

    const float* Qp = g_Q + ((size_t)b * NT + q0) * NH;
    const float* Kp = g_K + (size_t)b * NT * NH + (size_t)sp * (NT / SPLIT) * NH;
    const float* Vp = g_V + (size_t)b * NT * NH + (size_t)sp * (NT / SPLIT) * NH;

    const uint32_t smb = (uint32_t)__cvta_generic_to_shared(smem);
    const uint32_t qsb = smb;
    const uint32_t ksb = smb + 8192 * 4;
    const uint32_t vsb = smb + 16384 * 4;

    const int lr = t >> 4, lc = (t & 15) * 4;

#pragma unroll
    for (int i = 0; i < 16; i++)
        cp16(qsb + (uint32_t)SW(lr + 8 * i, lc) * 4,
             Qp + (size_t)(lr + 8 * i) * NH + lc);
#pragma unroll
    for (int i = 0; i < 8; i++)
        cp16(ksb + (uint32_t)SW(lr + 8 * i, lc) * 4,
             Kp + (size_t)(lr + 8 * i) * NH + lc);
    cp_commit();
#pragma unroll
    for (int i = 0; i < 8; i++)
        cp16(vsb + (uint32_t)SW(lr + 8 * i, lc) * 4,
             Vp + (size_t)(lr + 8 * i) * NH + lc);
    cp_commit();

    float o[2][8][4];
    float m[2][2], l[2][2];
#pragma unroll
    for (int mt = 0; mt < 2; mt++) {
        m[mt][0] = m[mt][1] = -1e30f;
        l[mt][0] = l[mt][1] = 0.0f;
#pragma unroll
        for (int nt = 0; nt < 8; nt++)
#pragma unroll
            for (int j = 0; j < 4; j++) o[mt][nt][j] = 0.0f;
    }

    const int NIT = (NT / SPLIT) / 64;  // 16

    for (int it = 0; it < NIT; it++) {
        const float* ksp = (it & 1) ? ks1 : ks0;
        const uint32_t knb = (it & 1) ? ksb : (ksb + 4096 * 4);
        cp_wait<1>();
        __syncthreads();
        if (it + 1 < NIT) {
#pragma unroll
            for (int i = 0; i < 8; i++)
                cp16(knb + (uint32_t)SW(lr + 8 * i, lc) * 4,
                     Kp + (size_t)((it + 1) * 64 + lr + 8 * i) * NH + lc);
        }
        cp_commit();

        float s[2][8][4];
#pragma unroll
        for (int mt = 0; mt < 2; mt++)
#pragma unroll
            for (int nt = 0; nt < 8; nt++)
                s[mt][nt][0] = s[mt][nt][1] = s[mt][nt][2] = s[mt][nt][3] = 0.0f;
#pragma unroll
        for (int kk8 = 0; kk8 < 8; kk8++) {
            int k0 = kk8 * 8;
            uint32_t a[2][4];
#pragma unroll
            for (int mt = 0; mt < 2; mt++) {
                int ar = r0 + 16 * mt;
                a[mt][0] = __float_as_uint(qs[SW(ar + g, k0 + t4)]);
                a[mt][1] = __float_as_uint(qs[SW(ar + g + 8, k0 + t4)]);
                a[mt][2] = __float_as_uint(qs[SW(ar + g, k0 + t4 + 4)]);
                a[mt][3] = __float_as_uint(qs[SW(ar + g + 8, k0 + t4 + 4)]);
            }
#pragma unroll
            for (int nt = 0; nt < 8; nt++) {
                uint32_t b0 = __float_as_uint(ksp[SW(nt * 8 + g, k0 + t4)]);
                uint32_t b1 = __float_as_uint(ksp[SW(nt * 8 + g, k0 + t4 + 4)]);
                mma8(s[0][nt], a[0][0], a[0][1], a[0][2], a[0][3], b0, b1);
                mma8(s[1][nt], a[1][0], a[1][1], a[1][2], a[1][3], b0, b1);
            }
        }

#pragma unroll
        for (int mt = 0; mt < 2; mt++) {
            float mx0 = -1e30f, mx1 = -1e30f;
#pragma unroll
            for (int nt = 0; nt < 8; nt++) {
                mx0 = fmaxf(mx0, fmaxf(s[mt][nt][0], s[mt][nt][1]));
                mx1 = fmaxf(mx1, fmaxf(s[mt][nt][2], s[mt][nt][3]));
            }
            mx0 = fmaxf(mx0, __shfl_xor_sync(0xffffffffu, mx0, 1));
            mx0 = fmaxf(mx0, __shfl_xor_sync(0xffffffffu, mx0, 2));
            mx1 = fmaxf(mx1, __shfl_xor_sync(0xffffffffu, mx1, 1));
            mx1 = fmaxf(mx1, __shfl_xor_sync(0xffffffffu, mx1, 2));
            float mn0 = fmaxf(m[mt][0], mx0), mn1 = fmaxf(m[mt][1], mx1);
            float c0 = __expf(m[mt][0] - mn0), c1 = __expf(m[mt][1] - mn1);
            float sum0 = 0.0f, sum1 = 0.0f;
#pragma unroll
            for (int nt = 0; nt < 8; nt++) {
                s[mt][nt][0] = __expf(s[mt][nt][0] - mn0);
                s[mt][nt][1] = __expf(s[mt][nt][1] - mn0);
                s[mt][nt][2] = __expf(s[mt][nt][2] - mn1);
                s[mt][nt][3] = __expf(s[mt][nt][3] - mn1);
                sum0 += s[mt][nt][0] + s[mt][nt][1];
                sum1 += s[mt][nt][2] + s[mt][nt][3];
                o[mt][nt][0] *= c0; o[mt][nt][1] *= c0;
                o[mt][nt][2] *= c1; o[mt][nt][3] *= c1;
            }
            sum0 += __shfl_xor_sync(0xffffffffu, sum0, 1);
            sum0 += __shfl_xor_sync(0xffffffffu, sum0, 2);
            sum1 += __shfl_xor_sync(0xffffffffu, sum1, 1);
            sum1 += __shfl_xor_sync(0xffffffffu, sum1, 2);
            l[mt][0] = l[mt][0] * c0 + sum0;
            l[mt][1] = l[mt][1] * c1 + sum1;
            m[mt][0] = mn0;
            m[mt][1] = mn1;
        }

        cp_wait<1>();
        __syncthreads();

#pragma unroll
        for (int kb = 0; kb < 8; kb++) {
            uint32_t a[2][4];
#pragma unroll
            for (int mt = 0; mt < 2; mt++) {
                a[mt][0] = f2tf(s[mt][kb][0]);
                a[mt][1] = f2tf(s[mt][kb][2]);
                a[mt][2] = f2tf(s[mt][kb][1]);
                a[mt][3] = f2tf(s[mt][kb][3]);
            }
#pragma unroll
            for (int nt = 0; nt < 8; nt++) {
                uint32_t b0 = __float_as_uint(vs[SW(kb * 8 + 2 * t4, nt * 8 + g)]);
                uint32_t b1 = __float_as_uint(vs[SW(kb * 8 + 2 * t4 + 1, nt * 8 + g)]);
                mma8(o[0][nt], a[0][0], a[0][1], a[0][2], a[0][3], b0, b1);
                mma8(o[1][nt], a[1][0], a[1][1], a[1][2], a[1][3], b0, b1);
            }
        }
        __syncthreads();

        if (it + 1 < NIT) {
#pragma unroll
            for (int i = 0; i < 8; i++)
                cp16(vsb + (uint32_t)SW(lr + 8 * i, lc) * 4,
                     Vp + (size_t)((it + 1) * 64 + lr + 8 * i) * NH + lc);
        }
        cp_commit();
    }

    float* Op = g_Op[sp] + ((size_t)b * NT + q0) * NH;
#pragma unroll
    for (int mt = 0; mt < 2; mt++) {
        int ar = r0 + 16 * mt;
#pragma unroll
        for (int nt = 0; nt < 8; nt++) {
            int c = nt * 8 + 2 * t4;
            *(float2*)&Op[(size_t)(ar + g) * NH + c] =
                make_float2(o[mt][nt][0], o[mt][nt][1]);
            *(float2*)&Op[(size_t)(ar + g + 8) * NH + c] =
                make_float2(o[mt][nt][2], o[mt][nt][3]);
        }
        if (t4 == 0) {
            int rr = b * NT + q0;
            g_ml[sp][rr + ar + g][0] = m[mt][0];
            g_ml[sp][rr + ar + g][1] = l[mt][0];
            g_ml[sp][rr + ar + g + 8][0] = m[mt][1];
            g_ml[sp][rr + ar + g + 8][1] = l[mt][1];
        }
    }
}

// ---------------------------------------------------------------------------
// Kernel 3: merge the SPLIT KV-splits.
// ---------------------------------------------------------------------------
__global__ __launch_bounds__(256) void combine_kernel(float* __restrict__ out)
{
    int row = blockIdx.x * 4 + (threadIdx.x >> 6);
    int c = threadIdx.x & 63;
    float M = -1e30f;
#pragma unroll
    for (int sp = 0; sp < SPLIT; sp++) M = fmaxf(M, g_ml[sp][row][0]);
    float L = 0.0f, acc = 0.0f;
    size_t idx = (size_t)row * NH + c;
#pragma unroll
    for (int sp = 0; sp < SPLIT; sp++) {
        float e = __expf(g_ml[sp][row][0] - M);
        L += e * g_ml[sp][row][1];
        acc += e * g_Op[sp][idx];
    }
    out[idx] = acc / L;
}

// ---------------------------------------------------------------------------
extern "C" void kernel_launch(void* const* d_in, const int* in_sizes, int n_in,
                              void* d_out, int out_size)
{
    const float* x  = (const float*)d_in[0];
    const float* wq = (const float*)d_in[1];
    const float* wk = (const float*)d_in[2];
    const float* wv = (const float*)d_in[3];
    float* out = (float*)d_out;
    (void)in_sizes; (void)n_in; (void)out_size;

    cudaFuncSetAttribute((const void*)qkv_kernel,
                         cudaFuncAttributeMaxDynamicSharedMemorySize,
                         QKV_SMEM_BYTES);
    cudaFuncSetAttribute((const void*)attn_kernel,
                         cudaFuncAttributeMaxDynamicSharedMemorySize,
                         ATTN_SMEM_BYTES);
    cudaFuncSetAttribute((const void*)attn_kernel,
                         cudaFuncAttributePreferredSharedMemoryCarveout,
                         cudaSharedmemCarveoutMaxShared);

    prep_w_kernel<<<(192 * ND) / 256, 256>>>(wq, wk, wv);
    qkv_kernel<<<(NB * NT) / 64, 256, QKV_SMEM_BYTES>>>(x);
    attn_kernel<<<dim3(NT / 128, NB, SPLIT), 128, ATTN_SMEM_BYTES>>>();
    combine_kernel<<<(NB * NT) / 4, 256>>>(out);
}